// round 14
// baseline (speedup 1.0000x reference)
#include <cuda_runtime.h>
#include <math.h>

// Problem constants
#define BB     256
#define TT     4096
#define NN     8
#define TWO_N  16
#define PP     144      // 2N + 2N^2
#define HH     64

// latent/dlatent base table over tt in [0,1): 328 segments, lerp err ~4e-6
#define TPTS   329
#define TSEG   328
#define ROWF   36       // base table row stride (floats)

// expanded smem row: s[16] | ur[8] | vr[8] | psi | pad3 = 36 floats
#define ROWB   36
#define ROWB4  9

// 2 blocks per batch row, 256 thr, 8 samples/thread
#define GRID_MAIN 512
#define BLK       256
#define SPT       8

__device__ __align__(16) float g_table[TPTS * ROWF];     // latent|dlatent
__device__ double   g_partd[GRID_MAIN];
__device__ double   g_parts[GRID_MAIN];
__device__ unsigned g_cnt = 0;

// ---- packed f32x2 helpers ------------------------------------------------
typedef unsigned long long u64;
__device__ __forceinline__ u64 fma2(u64 a, u64 b, u64 c) {
    u64 d; asm("fma.rn.f32x2 %0, %1, %2, %3;" : "=l"(d) : "l"(a), "l"(b), "l"(c)); return d;
}
__device__ __forceinline__ u64 pack2(float lo, float hi) {
    u64 d; asm("mov.b64 %0, {%1, %2};" : "=l"(d) : "f"(lo), "f"(hi)); return d;
}
union F4 { float4 v; u64 u[2]; };

// one float4 lerp: r = a0 + f*(a1-a0)  (as fma(f,a1, fma(-f,a0,a0)))
__device__ __forceinline__ float4 lerp4(const float4* base, int q, u64 f2, u64 mf2) {
    F4 a0, a1, r;
    a0.v = base[q]; a1.v = base[q + ROWB4];
    r.u[0] = fma2(f2, a1.u[0], fma2(mf2, a0.u[0], a0.u[0]));
    r.u[1] = fma2(f2, a1.u[1], fma2(mf2, a0.u[1], a0.u[1]));
    return r.v;
}

// ---------------------------------------------------------------------------
// Kernel 1: latent/dlatent vs tt (4 points / 256-thread block)
// ---------------------------------------------------------------------------
__global__ void table_kernel(const float* __restrict__ W1, const float* __restrict__ b1,
                             const float* __restrict__ W2, const float* __restrict__ b2) {
    __shared__ float sW2[HH * TWO_N];
    __shared__ float sb2[TWO_N];
    __shared__ float sh[4][HH];
    __shared__ float sdh[4][HH];
    const int tid = threadIdx.x;
    const int sub = tid >> 6;
    const int k   = tid & 63;
    const int m   = blockIdx.x * 4 + sub;

    for (int i = tid; i < HH * TWO_N; i += BLK) sW2[i] = W2[i];
    if (tid < TWO_N) sb2[tid] = b2[tid];

    float tt = (float)m * (1.0f / (float)TSEG);
    float w  = W1[k];
    float h  = tanhf(fmaf(tt, w, b1[k]));
    sh[sub][k]  = h;
    sdh[sub][k] = (1.0f - h * h) * w;
    __syncthreads();

    if (k < TWO_N && m < TPTS) {
        float lat = sb2[k];
        float dl  = 0.0f;
#pragma unroll
        for (int j = 0; j < HH; j++) {
            float w2 = sW2[j * TWO_N + k];
            lat = fmaf(sh[sub][j],  w2, lat);
            dl  = fmaf(sdh[sub][j], w2, dl);
        }
        g_table[m * ROWF + k]         = lat;
        g_table[m * ROWF + TWO_N + k] = dl;
    }
}

// ---------------------------------------------------------------------------
// Kernel 2: main loss. Each block expands its b's residual table in smem,
// then runs a register-lean sample loop. Fused deterministic final reduction.
// ---------------------------------------------------------------------------
__global__ void __launch_bounds__(BLK, 4)
main_kernel(const float* __restrict__ t_in,
            const float* __restrict__ x_target,
            const float* __restrict__ params_pred,
            const float* __restrict__ params_target,
            const float* __restrict__ ic_pred,
            const float* __restrict__ ic_target,
            float* __restrict__ out) {
    __shared__ __align__(16) float s_tab[TPTS * ROWB];   // 47376 B (aliased for final red.)
    __shared__ float  s_par[PP];
    __shared__ double s_red[BLK / 32];
    __shared__ double s_sup[80];
    __shared__ int    s_flag;

    const int tid   = threadIdx.x;
    const int b     = blockIdx.x >> 1;
    const int chunk = blockIdx.x & 1;

    if (tid < PP) s_par[tid] = params_pred[b * PP + tid];
    __syncthreads();

    // ---- in-block expansion: base table (L2-hot) -> residual table in smem
    {
        const float* g_  = s_par;
        const float* mu_ = s_par + 8;
        const float* Pi_ = s_par + 16;
        const float* Ga_ = s_par + 80;
        for (int m = tid; m < TPTS; m += BLK) {
            const float* row = g_table + m * ROWF;
            float a[NN], x[NN];
#pragma unroll
            for (int i = 0; i < NN; i++) {
                a[i] = row[i];
                x[i] = fmaxf(row[NN + i] - mu_[i], 0.0f);
            }
            float* o = s_tab + m * ROWB;
            float psi = 0.0f;
#pragma unroll
            for (int i = 0; i < NN; i++) {
                o[i]      = a[i];
                o[NN + i] = x[i];
                float pix = 0.0f, ga = 0.0f;
#pragma unroll
                for (int j = 0; j < NN; j++) {
                    pix = fmaf(Pi_[i * NN + j], x[j], pix);
                    ga  = fmaf(Ga_[i * NN + j], a[j], ga);
                }
                float e1 = row[TWO_N + i] - g_[i] - pix + a[i];
                psi = fmaf(e1, e1, psi);
                o[TWO_N + i]      = row[TWO_N + NN + i] - ga * (mu_[i] - x[i]); // e2 pos
                o[TWO_N + NN + i] = -ga * mu_[i];                               // e2 neg
            }
            o[32] = psi;
        }
    }
    __syncthreads();

    // ---- sample loop (register-lean: consume each lerped pack immediately)
    const float*  tbase  = t_in + b * TT + chunk * (SPT * BLK);
    const float*  xtbase = x_target + (size_t)b * TWO_N * TT + chunk * (SPT * BLK);
    float acc = 0.0f;

#pragma unroll 2
    for (int it = 0; it < SPT; it++) {
        const int toff = it * BLK + tid;
        float u  = tbase[toff] * (float)TSEG;
        int   i0 = (int)u;
        i0 = min(max(i0, 0), TPTS - 2);
        const float f = u - (float)i0;
        const u64 f2  = pack2(f, f);
        const u64 mf2 = pack2(-f, -f);

        const float4* r0 = (const float4*)s_tab + i0 * ROWB4;
        const float*  xt = xtbase + toff;

        // a-part data loss (packs 0..1), consumed immediately
#pragma unroll
        for (int q = 0; q < 2; q++) {
            float4 v = lerp4(r0, q, f2, mf2);
            float d0 = v.x - xt[(q*4+0) * TT];
            float d1 = v.y - xt[(q*4+1) * TT];
            float d2 = v.z - xt[(q*4+2) * TT];
            float d3 = v.w - xt[(q*4+3) * TT];
            acc = fmaf(d0, d0, acc); acc = fmaf(d1, d1, acc);
            acc = fmaf(d2, d2, acc); acc = fmaf(d3, d3, acc);
        }
        // x-part data loss (packs 2..3); keep only gate values
        float xg[NN];
#pragma unroll
        for (int q = 0; q < 2; q++) {
            float4 v = lerp4(r0, 2 + q, f2, mf2);
            xg[q*4+0] = v.x; xg[q*4+1] = v.y; xg[q*4+2] = v.z; xg[q*4+3] = v.w;
            float d0 = v.x - xt[(NN+q*4+0) * TT];
            float d1 = v.y - xt[(NN+q*4+1) * TT];
            float d2 = v.z - xt[(NN+q*4+2) * TT];
            float d3 = v.w - xt[(NN+q*4+3) * TT];
            acc = fmaf(d0, d0, acc); acc = fmaf(d1, d1, acc);
            acc = fmaf(d2, d2, acc); acc = fmaf(d3, d3, acc);
        }
        // gated e2: lerp ur/vr pack-pairwise, select on exact gate, consume
#pragma unroll
        for (int q = 0; q < 2; q++) {
            float4 ur = lerp4(r0, 4 + q, f2, mf2);
            float4 vr = lerp4(r0, 6 + q, f2, mf2);
            float e0 = (xg[q*4+0] > 0.0f) ? ur.x : vr.x;
            float e1 = (xg[q*4+1] > 0.0f) ? ur.y : vr.y;
            float e2 = (xg[q*4+2] > 0.0f) ? ur.z : vr.z;
            float e3 = (xg[q*4+3] > 0.0f) ? ur.w : vr.w;
            acc = fmaf(e0, e0, acc); acc = fmaf(e1, e1, acc);
            acc = fmaf(e2, e2, acc); acc = fmaf(e3, e3, acc);
        }
        // psi scalar lerp
        float p0 = s_tab[i0 * ROWB + 32];
        float p1 = s_tab[i0 * ROWB + ROWB + 32];
        acc += fmaf(f, p1 - p0, p0);
    }

    // supervised slice: 80 elements/block covers B*160 = 40960 exactly
    if (tid < 80) {
        int idx = blockIdx.x * 80 + tid;
        int row = idx / 160;
        int col = idx - row * 160;
        float d;
        if (col < PP) d = params_pred[row * PP + col] - params_target[row * PP + col];
        else          d = ic_pred[row * TWO_N + (col - PP)] - ic_target[row * TWO_N + (col - PP)];
        s_sup[tid] = (double)d * (double)d;
    }

    // deterministic block reduction
    double v = (double)acc;
#pragma unroll
    for (int off = 16; off > 0; off >>= 1)
        v += __shfl_down_sync(0xFFFFFFFFu, v, off);
    if ((tid & 31) == 0) s_red[tid >> 5] = v;
    __syncthreads();
    if (tid == 0) {
        double s = 0.0;
#pragma unroll
        for (int w = 0; w < BLK / 32; w++) s += s_red[w];
        g_partd[blockIdx.x] = s;
        double sp = 0.0;
        for (int j = 0; j < 80; j++) sp += s_sup[j];
        g_parts[blockIdx.x] = sp;
        __threadfence();
        unsigned old = atomicAdd(&g_cnt, 1u);
        s_flag = (old == GRID_MAIN - 1) ? 1 : 0;
    }
    __syncthreads();

    // last block: deterministic final reduction (aliases s_tab)
    if (s_flag) {
        __threadfence();
        double* s1 = (double*)s_tab;
        double* s2 = s1 + (BLK / 32);
        double a = 0.0, c = 0.0;
        for (int i = tid; i < GRID_MAIN; i += BLK) { a += g_partd[i]; c += g_parts[i]; }
#pragma unroll
        for (int off = 16; off > 0; off >>= 1) {
            a += __shfl_down_sync(0xFFFFFFFFu, a, off);
            c += __shfl_down_sync(0xFFFFFFFFu, c, off);
        }
        if ((tid & 31) == 0) { s1[tid >> 5] = a; s2[tid >> 5] = c; }
        __syncthreads();
        if (tid == 0) {
            double t1 = 0.0, t2 = 0.0;
#pragma unroll
            for (int w = 0; w < BLK / 32; w++) { t1 += s1[w]; t2 += s2[w]; }
            double loss = t1 / (double)((size_t)BB * TWO_N * TT)
                        + t2 / (double)(BB * 160);
            out[0] = (float)loss;
            g_cnt  = 0;      // reset for next graph replay
        }
    }
}

// ---------------------------------------------------------------------------
extern "C" void kernel_launch(void* const* d_in, const int* in_sizes, int n_in,
                              void* d_out, int out_size) {
    const float* t_in          = (const float*)d_in[0];
    const float* x_target      = (const float*)d_in[1];
    const float* params_pred   = (const float*)d_in[2];
    const float* params_target = (const float*)d_in[3];
    const float* ic_pred       = (const float*)d_in[4];
    const float* ic_target     = (const float*)d_in[5];
    const float* W1            = (const float*)d_in[6];
    const float* b1            = (const float*)d_in[7];
    const float* W2            = (const float*)d_in[8];
    const float* b2            = (const float*)d_in[9];

    table_kernel<<<(TPTS + 3) / 4, BLK>>>(W1, b1, W2, b2);
    main_kernel<<<GRID_MAIN, BLK>>>(t_in, x_target, params_pred, params_target,
                                    ic_pred, ic_target, (float*)d_out);
}